// round 3
// baseline (speedup 1.0000x reference)
#include <cuda_runtime.h>

// MiniTransformer: B=131072 batch, T=8, D=32, H=64, V=27, all fp32.
// Strategy: one warp per batch element, lane j = feature dim j.
// Weights staged in shared once per block; per-warp shared scratch used as
// broadcast source for the tiny matmuls; warp shuffles for attention scores
// and layernorm reductions.

namespace {
constexpr int T = 8;
constexpr int D = 32;
constexpr int H = 64;
constexpr int V = 27;
constexpr float EPS = 1e-5f;
constexpr int NWARP = 4;     // warps per block
constexpr int SCR = 64;      // scratch row stride (floats) - fits the 8x64 y1 tile
constexpr int GRID = 1480;
}

__global__ __launch_bounds__(NWARP * 32) void mt_kernel(
    const int*   __restrict__ tokens,
    const float* __restrict__ tok_emb,
    const float* __restrict__ pos_emb,
    const float* __restrict__ gWq,
    const float* __restrict__ gWk,
    const float* __restrict__ gWv,
    const float* __restrict__ gW1,
    const float* __restrict__ gW2,
    const float* __restrict__ gWo,
    float* __restrict__ out,
    int nB, int nwarps_total)
{
    __shared__ float sTE[V * D];          // 864
    __shared__ float sPos[T * D];         // 256
    __shared__ float sWq[D * D];          // 1024
    __shared__ float sWk[D * D];
    __shared__ float sWv[D * D];
    __shared__ float sW1[D * H];          // 2048
    __shared__ float sW2[H * D];          // 2048
    __shared__ float sWo[D * 32];         // Wout padded to 32 cols (zeros j>=27)
    __shared__ float scr_all[NWARP][T * SCR];

    const int tid = threadIdx.x;
    const int nthr = NWARP * 32;

    for (int i = tid; i < V * D; i += nthr) sTE[i] = tok_emb[i];
    for (int i = tid; i < T * D; i += nthr) sPos[i] = pos_emb[i];
    for (int i = tid; i < D * D; i += nthr) {
        sWq[i] = gWq[i];
        sWk[i] = gWk[i];
        sWv[i] = gWv[i];
    }
    for (int i = tid; i < D * H; i += nthr) sW1[i] = gW1[i];
    for (int i = tid; i < H * D; i += nthr) sW2[i] = gW2[i];
    for (int i = tid; i < D * 32; i += nthr) {
        int d = i >> 5, jv = i & 31;
        sWo[i] = (jv < V) ? gWo[d * V + jv] : 0.0f;
    }
    __syncthreads();

    const int j = tid & 31;
    float* scr = scr_all[tid >> 5];
    const int warp_global = blockIdx.x * NWARP + (tid >> 5);

    for (int b = warp_global; b < nB; b += nwarps_total) {
        // ---- embeddings: x[t][j] = tok_emb[tok_t][j] + pos_emb[t][j] ----
        int mytok = 0;
        if (j < T) mytok = tokens[b * T + j];

        float x[T];
        #pragma unroll
        for (int t = 0; t < T; ++t) {
            int tok = __shfl_sync(0xffffffffu, mytok, t);
            x[t] = sTE[tok * D + j] + sPos[t * D + j];
            scr[t * SCR + j] = x[t];
        }
        __syncwarp();

        // ---- Q,K,V = x @ {Wq,Wk,Wv}  (lane j holds column j) ----
        float q[T], k[T], v[T];
        #pragma unroll
        for (int t = 0; t < T; ++t) { q[t] = 0.f; k[t] = 0.f; v[t] = 0.f; }

        #pragma unroll
        for (int dc = 0; dc < D / 4; ++dc) {
            float4 xv[T];
            #pragma unroll
            for (int t = 0; t < T; ++t)
                xv[t] = *(const float4*)&scr[t * SCR + dc * 4];
            #pragma unroll
            for (int i = 0; i < 4; ++i) {
                const int d = dc * 4 + i;
                const float wq = sWq[d * D + j];
                const float wk = sWk[d * D + j];
                const float wv = sWv[d * D + j];
                #pragma unroll
                for (int t = 0; t < T; ++t) {
                    const float xd = (i == 0) ? xv[t].x
                                   : (i == 1) ? xv[t].y
                                   : (i == 2) ? xv[t].z : xv[t].w;
                    q[t] = fmaf(xd, wq, q[t]);
                    k[t] = fmaf(xd, wk, k[t]);
                    v[t] = fmaf(xd, wv, v[t]);
                }
            }
        }

        // ---- causal attention, per query position t ----
        float o[T];
        #pragma unroll
        for (int t = 0; t < T; ++t) {
            float e[T];
            float m = -1e30f;
            #pragma unroll
            for (int s = 0; s < T; ++s) {
                if (s <= t) {
                    float p = q[t] * k[s];
                    #pragma unroll
                    for (int off = 16; off > 0; off >>= 1)
                        p += __shfl_xor_sync(0xffffffffu, p, off);
                    e[s] = p;
                    m = fmaxf(m, p);
                }
            }
            float den = 0.0f;
            #pragma unroll
            for (int s = 0; s < T; ++s) {
                if (s <= t) {
                    e[s] = __expf(e[s] - m);
                    den += e[s];
                }
            }
            float acc = 0.0f;
            #pragma unroll
            for (int s = 0; s < T; ++s)
                if (s <= t) acc = fmaf(e[s], v[s], acc);
            o[t] = acc * (1.0f / den);
        }

        // ---- residual + LayerNorm 1 (reduce over 32 lanes) ----
        float ln1[T];
        #pragma unroll
        for (int t = 0; t < T; ++t) {
            float h = o[t] + x[t];
            float s1 = h, s2 = h * h;
            #pragma unroll
            for (int off = 16; off > 0; off >>= 1) {
                s1 += __shfl_xor_sync(0xffffffffu, s1, off);
                s2 += __shfl_xor_sync(0xffffffffu, s2, off);
            }
            float mu  = s1 * (1.0f / D);
            float var = s2 * (1.0f / D) - mu * mu;
            float r = rsqrtf(var + EPS);
            ln1[t] = (h - mu) * r;
        }
        __syncwarp();
        #pragma unroll
        for (int t = 0; t < T; ++t) scr[t * SCR + j] = ln1[t];
        __syncwarp();

        // ---- MLP up: y1 = relu(ln1 @ W1), lane j holds cols j and j+32 ----
        float ya[T], yb[T];
        #pragma unroll
        for (int t = 0; t < T; ++t) { ya[t] = 0.f; yb[t] = 0.f; }

        #pragma unroll
        for (int dc = 0; dc < D / 4; ++dc) {
            float4 av[T];
            #pragma unroll
            for (int t = 0; t < T; ++t)
                av[t] = *(const float4*)&scr[t * SCR + dc * 4];
            #pragma unroll
            for (int i = 0; i < 4; ++i) {
                const int d = dc * 4 + i;
                const float wa = sW1[d * H + j];
                const float wb = sW1[d * H + j + 32];
                #pragma unroll
                for (int t = 0; t < T; ++t) {
                    const float ad = (i == 0) ? av[t].x
                                   : (i == 1) ? av[t].y
                                   : (i == 2) ? av[t].z : av[t].w;
                    ya[t] = fmaf(ad, wa, ya[t]);
                    yb[t] = fmaf(ad, wb, yb[t]);
                }
            }
        }
        __syncwarp();
        #pragma unroll
        for (int t = 0; t < T; ++t) {
            scr[t * SCR + j]      = fmaxf(ya[t], 0.0f);
            scr[t * SCR + j + 32] = fmaxf(yb[t], 0.0f);
        }
        __syncwarp();

        // ---- MLP down: y2 = y1 @ W2 ----
        float y2[T];
        #pragma unroll
        for (int t = 0; t < T; ++t) y2[t] = 0.f;

        #pragma unroll
        for (int hc = 0; hc < H / 4; ++hc) {
            float4 av[T];
            #pragma unroll
            for (int t = 0; t < T; ++t)
                av[t] = *(const float4*)&scr[t * SCR + hc * 4];
            #pragma unroll
            for (int i = 0; i < 4; ++i) {
                const int h = hc * 4 + i;
                const float w = sW2[h * D + j];
                #pragma unroll
                for (int t = 0; t < T; ++t) {
                    const float ad = (i == 0) ? av[t].x
                                   : (i == 1) ? av[t].y
                                   : (i == 2) ? av[t].z : av[t].w;
                    y2[t] = fmaf(ad, w, y2[t]);
                }
            }
        }

        // ---- residual + LayerNorm 2 ----
        float z[T];
        #pragma unroll
        for (int t = 0; t < T; ++t) {
            float h = y2[t] + ln1[t];
            float s1 = h, s2 = h * h;
            #pragma unroll
            for (int off = 16; off > 0; off >>= 1) {
                s1 += __shfl_xor_sync(0xffffffffu, s1, off);
                s2 += __shfl_xor_sync(0xffffffffu, s2, off);
            }
            float mu  = s1 * (1.0f / D);
            float var = s2 * (1.0f / D) - mu * mu;
            float r = rsqrtf(var + EPS);
            z[t] = (h - mu) * r;
        }
        __syncwarp();
        #pragma unroll
        for (int t = 0; t < T; ++t) scr[t * SCR + j] = z[t];
        __syncwarp();

        // ---- logits = z @ Wout (Wout zero-padded to 32 cols) ----
        float lg[T];
        #pragma unroll
        for (int t = 0; t < T; ++t) lg[t] = 0.f;

        #pragma unroll
        for (int dc = 0; dc < D / 4; ++dc) {
            float4 av[T];
            #pragma unroll
            for (int t = 0; t < T; ++t)
                av[t] = *(const float4*)&scr[t * SCR + dc * 4];
            #pragma unroll
            for (int i = 0; i < 4; ++i) {
                const int d = dc * 4 + i;
                const float w = sWo[d * 32 + j];
                #pragma unroll
                for (int t = 0; t < T; ++t) {
                    const float ad = (i == 0) ? av[t].x
                                   : (i == 1) ? av[t].y
                                   : (i == 2) ? av[t].z : av[t].w;
                    lg[t] = fmaf(ad, w, lg[t]);
                }
            }
        }
        __syncwarp();   // scr gets overwritten at top of next iteration

        if (j < V) {
            const size_t base = (size_t)b * (T * V);
            #pragma unroll
            for (int t = 0; t < T; ++t)
                out[base + t * V + j] = lg[t];
        }
    }
}

extern "C" void kernel_launch(void* const* d_in, const int* in_sizes, int n_in,
                              void* d_out, int out_size)
{
    const int*   tokens  = (const int*)  d_in[0];
    const float* tok_emb = (const float*)d_in[1];
    const float* pos_emb = (const float*)d_in[2];
    const float* Wq      = (const float*)d_in[3];
    const float* Wk      = (const float*)d_in[4];
    const float* Wv      = (const float*)d_in[5];
    const float* W1      = (const float*)d_in[6];
    const float* W2      = (const float*)d_in[7];
    const float* Wout    = (const float*)d_in[8];
    float* out = (float*)d_out;

    const int nB = in_sizes[0] / T;
    const int nwarps_total = GRID * NWARP;

    mt_kernel<<<GRID, NWARP * 32>>>(tokens, tok_emb, pos_emb,
                                    Wq, Wk, Wv, W1, W2, Wout,
                                    out, nB, nwarps_total);
}

// round 7
// speedup vs baseline: 1.2962x; 1.2962x over previous
#include <cuda_runtime.h>

// MiniTransformer B=131072, T=8, D=32, H=64, V=27, fp32.
// Warp-per-batch, lane j = feature dim.
//  - matmuls use packed fma.rn.f32x2 over t-pairs (activations stored
//    transposed in shared, weights duplicated per-register via mov.b64)
//  - 32-lane reductions: shfl_xor butterfly (redux.f32 does NOT exist on
//    sm_103 -- R3 lesson). LayerNorm packs (sum, sumsq) into one f32x2
//    butterfly so the two sums share one add per step.

namespace {
constexpr int T = 8;
constexpr int D = 32;
constexpr int H = 64;
constexpr int V = 27;
constexpr float EPS = 1e-5f;
constexpr int NWARP = 4;
constexpr int STR = 12;       // transposed scratch row stride (floats)
constexpr int GRID = 1480;
}

__device__ __forceinline__ unsigned long long pack2(float a) {
    unsigned long long r;
    asm("mov.b64 %0, {%1, %1};" : "=l"(r) : "f"(a));
    return r;
}
__device__ __forceinline__ unsigned long long pack2f(float a, float b) {
    unsigned long long r;
    asm("mov.b64 %0, {%1, %2};" : "=l"(r) : "f"(a), "f"(b));
    return r;
}
__device__ __forceinline__ void unpack2(unsigned long long p, float& a, float& b) {
    asm("mov.b64 {%0, %1}, %2;" : "=f"(a), "=f"(b) : "l"(p));
}
__device__ __forceinline__ unsigned long long add2(unsigned long long a,
                                                   unsigned long long b) {
    unsigned long long r;
    asm("add.rn.f32x2 %0, %1, %2;" : "=l"(r) : "l"(a), "l"(b));
    return r;
}
__device__ __forceinline__ void ffma2(unsigned long long& d,
                                      unsigned long long a,
                                      unsigned long long b) {
    asm("fma.rn.f32x2 %0, %1, %2, %0;" : "+l"(d) : "l"(a), "l"(b));
}
__device__ __forceinline__ float warp_sum(float v) {
    #pragma unroll
    for (int off = 16; off > 0; off >>= 1)
        v += __shfl_xor_sync(0xffffffffu, v, off);
    return v;
}
// packed butterfly: reduces both halves of an f32x2 across the warp
__device__ __forceinline__ unsigned long long warp_sum2(unsigned long long p) {
    #pragma unroll
    for (int off = 16; off > 0; off >>= 1) {
        unsigned long long o = __shfl_xor_sync(0xffffffffu, p, off);
        p = add2(p, o);
    }
    return p;
}

union Pack8 {                  // 8 floats = 4 f32x2 pairs (t0..t7)
    unsigned long long u[4];
    float f[8];
    float4 v4[2];
};

__global__ __launch_bounds__(NWARP * 32) void mt_kernel(
    const int*   __restrict__ tokens,
    const float* __restrict__ tok_emb,
    const float* __restrict__ pos_emb,
    const float* __restrict__ gWq,
    const float* __restrict__ gWk,
    const float* __restrict__ gWv,
    const float* __restrict__ gW1,
    const float* __restrict__ gW2,
    const float* __restrict__ gWo,
    float* __restrict__ out,
    int nB, int nwarps_total)
{
    __shared__ float sTE[V * D];
    __shared__ float sPos[T * D];
    __shared__ float sWq[D * D];
    __shared__ float sWk[D * D];
    __shared__ float sWv[D * D];
    __shared__ float sW1[D * H];
    __shared__ float sW2[H * D];
    __shared__ float sWo[D * 32];              // Wout padded to 32 cols
    __shared__ float scrT_all[NWARP][H * STR]; // transposed scratch [dim][t]

    const int tid = threadIdx.x;
    const int nthr = NWARP * 32;

    for (int i = tid; i < V * D; i += nthr) sTE[i] = tok_emb[i];
    for (int i = tid; i < T * D; i += nthr) sPos[i] = pos_emb[i];
    for (int i = tid; i < D * D; i += nthr) {
        sWq[i] = gWq[i];
        sWk[i] = gWk[i];
        sWv[i] = gWv[i];
    }
    for (int i = tid; i < D * H; i += nthr) sW1[i] = gW1[i];
    for (int i = tid; i < H * D; i += nthr) sW2[i] = gW2[i];
    for (int i = tid; i < D * 32; i += nthr) {
        int d = i >> 5, jv = i & 31;
        sWo[i] = (jv < V) ? gWo[d * V + jv] : 0.0f;
    }
    __syncthreads();

    const int j = tid & 31;
    float* scrT = scrT_all[tid >> 5];
    const int warp_global = blockIdx.x * NWARP + (tid >> 5);

    for (int b = warp_global; b < nB; b += nwarps_total) {
        // ---- embeddings: X.f[t] = tok_emb[tok_t][j] + pos_emb[t][j] ----
        int mytok = 0;
        if (j < T) mytok = tokens[b * T + j];

        Pack8 X;
        #pragma unroll
        for (int t = 0; t < T; ++t) {
            int tok = __shfl_sync(0xffffffffu, mytok, t);
            X.f[t] = sTE[tok * D + j] + sPos[t * D + j];
        }
        __syncwarp();
        *(float4*)&scrT[j * STR]     = X.v4[0];
        *(float4*)&scrT[j * STR + 4] = X.v4[1];
        __syncwarp();

        // ---- Q,K,V = x @ {Wq,Wk,Wv}, packed over t-pairs ----
        Pack8 Q, K, Vv;
        #pragma unroll
        for (int i = 0; i < 4; ++i) { Q.u[i] = 0ull; K.u[i] = 0ull; Vv.u[i] = 0ull; }

        #pragma unroll
        for (int d = 0; d < D; ++d) {
            Pack8 xp;
            xp.v4[0] = *(const float4*)&scrT[d * STR];
            xp.v4[1] = *(const float4*)&scrT[d * STR + 4];
            const unsigned long long wq = pack2(sWq[d * D + j]);
            const unsigned long long wk = pack2(sWk[d * D + j]);
            const unsigned long long wv = pack2(sWv[d * D + j]);
            #pragma unroll
            for (int i = 0; i < 4; ++i) {
                ffma2(Q.u[i],  xp.u[i], wq);
                ffma2(K.u[i],  xp.u[i], wk);
                ffma2(Vv.u[i], xp.u[i], wv);
            }
        }

        // ---- causal attention ----
        float o[T];
        #pragma unroll
        for (int t = 0; t < T; ++t) {
            float e[T];
            float m = -1e30f;
            #pragma unroll
            for (int s = 0; s < T; ++s) {
                if (s <= t) {
                    float p = warp_sum(Q.f[t] * K.f[s]);
                    e[s] = p;
                    m = fmaxf(m, p);
                }
            }
            float den = 0.0f;
            #pragma unroll
            for (int s = 0; s < T; ++s) {
                if (s <= t) {
                    e[s] = __expf(e[s] - m);
                    den += e[s];
                }
            }
            float acc = 0.0f;
            #pragma unroll
            for (int s = 0; s < T; ++s)
                if (s <= t) acc = fmaf(e[s], Vv.f[s], acc);
            o[t] = acc * (1.0f / den);
        }

        // ---- residual + LayerNorm 1 (packed sum/sumsq butterfly) ----
        Pack8 L;
        #pragma unroll
        for (int t = 0; t < T; ++t) {
            float h = o[t] + X.f[t];
            float s1, s2;
            unpack2(warp_sum2(pack2f(h, h * h)), s1, s2);
            float mu  = s1 * (1.0f / D);
            float var = s2 * (1.0f / D) - mu * mu;
            L.f[t] = (h - mu) * rsqrtf(var + EPS);
        }
        __syncwarp();
        *(float4*)&scrT[j * STR]     = L.v4[0];
        *(float4*)&scrT[j * STR + 4] = L.v4[1];
        __syncwarp();

        // ---- MLP up: y1 = relu(ln1 @ W1); lane j owns cols j and j+32 ----
        Pack8 Ya, Yb;
        #pragma unroll
        for (int i = 0; i < 4; ++i) { Ya.u[i] = 0ull; Yb.u[i] = 0ull; }

        #pragma unroll
        for (int d = 0; d < D; ++d) {
            Pack8 xp;
            xp.v4[0] = *(const float4*)&scrT[d * STR];
            xp.v4[1] = *(const float4*)&scrT[d * STR + 4];
            const unsigned long long wa = pack2(sW1[d * H + j]);
            const unsigned long long wb = pack2(sW1[d * H + j + 32]);
            #pragma unroll
            for (int i = 0; i < 4; ++i) {
                ffma2(Ya.u[i], xp.u[i], wa);
                ffma2(Yb.u[i], xp.u[i], wb);
            }
        }
        #pragma unroll
        for (int i = 0; i < 8; ++i) {
            Ya.f[i] = fmaxf(Ya.f[i], 0.0f);
            Yb.f[i] = fmaxf(Yb.f[i], 0.0f);
        }
        __syncwarp();
        *(float4*)&scrT[j * STR]            = Ya.v4[0];
        *(float4*)&scrT[j * STR + 4]        = Ya.v4[1];
        *(float4*)&scrT[(j + 32) * STR]     = Yb.v4[0];
        *(float4*)&scrT[(j + 32) * STR + 4] = Yb.v4[1];
        __syncwarp();

        // ---- MLP down: y2 = y1 @ W2 ----
        Pack8 Y2;
        #pragma unroll
        for (int i = 0; i < 4; ++i) Y2.u[i] = 0ull;

        #pragma unroll
        for (int h = 0; h < H; ++h) {
            Pack8 xp;
            xp.v4[0] = *(const float4*)&scrT[h * STR];
            xp.v4[1] = *(const float4*)&scrT[h * STR + 4];
            const unsigned long long w = pack2(sW2[h * D + j]);
            #pragma unroll
            for (int i = 0; i < 4; ++i)
                ffma2(Y2.u[i], xp.u[i], w);
        }

        // ---- residual + LayerNorm 2 ----
        Pack8 Z;
        #pragma unroll
        for (int t = 0; t < T; ++t) {
            float h = Y2.f[t] + L.f[t];
            float s1, s2;
            unpack2(warp_sum2(pack2f(h, h * h)), s1, s2);
            float mu  = s1 * (1.0f / D);
            float var = s2 * (1.0f / D) - mu * mu;
            Z.f[t] = (h - mu) * rsqrtf(var + EPS);
        }
        __syncwarp();
        *(float4*)&scrT[j * STR]     = Z.v4[0];
        *(float4*)&scrT[j * STR + 4] = Z.v4[1];
        __syncwarp();

        // ---- logits = z @ Wout (padded to 32 cols) ----
        Pack8 Lg;
        #pragma unroll
        for (int i = 0; i < 4; ++i) Lg.u[i] = 0ull;

        #pragma unroll
        for (int d = 0; d < D; ++d) {
            Pack8 xp;
            xp.v4[0] = *(const float4*)&scrT[d * STR];
            xp.v4[1] = *(const float4*)&scrT[d * STR + 4];
            const unsigned long long w = pack2(sWo[d * 32 + j]);
            #pragma unroll
            for (int i = 0; i < 4; ++i)
                ffma2(Lg.u[i], xp.u[i], w);
        }
        __syncwarp();   // scrT reused next iteration

        if (j < V) {
            const size_t base = (size_t)b * (T * V);
            #pragma unroll
            for (int t = 0; t < T; ++t)
                out[base + t * V + j] = Lg.f[t];
        }
    }
}

extern "C" void kernel_launch(void* const* d_in, const int* in_sizes, int n_in,
                              void* d_out, int out_size)
{
    const int*   tokens  = (const int*)  d_in[0];
    const float* tok_emb = (const float*)d_in[1];
    const float* pos_emb = (const float*)d_in[2];
    const float* Wq      = (const float*)d_in[3];
    const float* Wk      = (const float*)d_in[4];
    const float* Wv      = (const float*)d_in[5];
    const float* W1      = (const float*)d_in[6];
    const float* W2      = (const float*)d_in[7];
    const float* Wout    = (const float*)d_in[8];
    float* out = (float*)d_out;

    const int nB = in_sizes[0] / T;
    const int nwarps_total = GRID * NWARP;

    mt_kernel<<<GRID, NWARP * 32>>>(tokens, tok_emb, pos_emb,
                                    Wq, Wk, Wv, W1, W2, Wout,
                                    out, nB, nwarps_total);
}

// round 9
// speedup vs baseline: 1.4866x; 1.1469x over previous
#include <cuda_runtime.h>

// MiniTransformer B=131072, T=8, D=32, H=64, V=27, fp32.
// Warp-per-batch, lane j = feature dim.
//  - matmuls: packed fma.rn.f32x2 over t-pairs (transposed smem activations)
//  - attention: smem row dots per (t,s-pair) lane + quad softmax (replaces
//    180 butterfly SHFLs with ~58 MIO ops)
//  - layernorms: packed (sum,sumsq) f32x2 butterflies

namespace {
constexpr int T = 8;
constexpr int D = 32;
constexpr int H = 64;
constexpr int V = 27;
constexpr float EPS = 1e-5f;
constexpr int NWARP = 4;
constexpr int STR = 12;        // transposed activation tile row stride
constexpr int QS  = 36;        // Q/K score-row stride (bank-conflict-free)
constexpr int KB  = 288;       // K rows base (floats)
constexpr int AB  = 576;       // attn tile base (floats), stride 12
constexpr int GRID = 1480;
}

__device__ __forceinline__ unsigned long long pack2(float a) {
    unsigned long long r;
    asm("mov.b64 %0, {%1, %1};" : "=l"(r) : "f"(a));
    return r;
}
__device__ __forceinline__ unsigned long long pack2f(float a, float b) {
    unsigned long long r;
    asm("mov.b64 %0, {%1, %2};" : "=l"(r) : "f"(a), "f"(b));
    return r;
}
__device__ __forceinline__ void unpack2(unsigned long long p, float& a, float& b) {
    asm("mov.b64 {%0, %1}, %2;" : "=f"(a), "=f"(b) : "l"(p));
}
__device__ __forceinline__ unsigned long long add2(unsigned long long a,
                                                   unsigned long long b) {
    unsigned long long r;
    asm("add.rn.f32x2 %0, %1, %2;" : "=l"(r) : "l"(a), "l"(b));
    return r;
}
__device__ __forceinline__ void ffma2(unsigned long long& d,
                                      unsigned long long a,
                                      unsigned long long b) {
    asm("fma.rn.f32x2 %0, %1, %2, %0;" : "+l"(d) : "l"(a), "l"(b));
}
__device__ __forceinline__ unsigned long long warp_sum2(unsigned long long p) {
    #pragma unroll
    for (int off = 16; off > 0; off >>= 1) {
        unsigned long long o = __shfl_xor_sync(0xffffffffu, p, off);
        p = add2(p, o);
    }
    return p;
}

union Pack8 {                  // 8 floats = 4 f32x2 pairs (t0..t7)
    unsigned long long u[4];
    float f[8];
    float4 v4[2];
};
union Pack4 {                  // 4 floats = 2 f32x2 pairs
    unsigned long long u[2];
    float f[4];
    float4 v4;
};

__global__ __launch_bounds__(NWARP * 32, 4) void mt_kernel(
    const int*   __restrict__ tokens,
    const float* __restrict__ tok_emb,
    const float* __restrict__ pos_emb,
    const float* __restrict__ gWq,
    const float* __restrict__ gWk,
    const float* __restrict__ gWv,
    const float* __restrict__ gW1,
    const float* __restrict__ gW2,
    const float* __restrict__ gWo,
    float* __restrict__ out,
    int nB, int nwarps_total)
{
    __shared__ float sTE[V * D];
    __shared__ float sPos[T * D];
    __shared__ float sWq[D * D];
    __shared__ float sWk[D * D];
    __shared__ float sWv[D * D];
    __shared__ float sW1[D * H];
    __shared__ float sW2[H * D];
    __shared__ float sWo[D * 32];               // Wout padded to 32 cols
    __shared__ __align__(16) float scrT_all[NWARP][H * STR];  // 768 f/warp

    const int tid = threadIdx.x;
    const int nthr = NWARP * 32;

    for (int i = tid; i < V * D; i += nthr) sTE[i] = tok_emb[i];
    for (int i = tid; i < T * D; i += nthr) sPos[i] = pos_emb[i];
    for (int i = tid; i < D * D; i += nthr) {
        sWq[i] = gWq[i];
        sWk[i] = gWk[i];
        sWv[i] = gWv[i];
    }
    for (int i = tid; i < D * H; i += nthr) sW1[i] = gW1[i];
    for (int i = tid; i < H * D; i += nthr) sW2[i] = gW2[i];
    for (int i = tid; i < D * 32; i += nthr) {
        int d = i >> 5, jv = i & 31;
        sWo[i] = (jv < V) ? gWo[d * V + jv] : 0.0f;
    }
    __syncthreads();

    const int j = tid & 31;
    float* scrT = scrT_all[tid >> 5];
    const int warp_global = blockIdx.x * NWARP + (tid >> 5);

    const int tq = j >> 2;      // this lane's query row for attention
    const int p  = j & 3;       // this lane's s-pair index

    for (int b = warp_global; b < nB; b += nwarps_total) {
        // ---- embeddings ----
        int mytok = 0;
        if (j < T) mytok = tokens[b * T + j];

        Pack8 X;
        #pragma unroll
        for (int t = 0; t < T; ++t) {
            int tok = __shfl_sync(0xffffffffu, mytok, t);
            X.f[t] = sTE[tok * D + j] + sPos[t * D + j];
        }
        __syncwarp();
        *(float4*)&scrT[j * STR]     = X.v4[0];
        *(float4*)&scrT[j * STR + 4] = X.v4[1];
        __syncwarp();

        // ---- Q,K,V = x @ {Wq,Wk,Wv}, packed over t-pairs ----
        Pack8 Q, K, Vv;
        #pragma unroll
        for (int i = 0; i < 4; ++i) { Q.u[i] = 0ull; K.u[i] = 0ull; Vv.u[i] = 0ull; }

        #pragma unroll
        for (int d = 0; d < D; ++d) {
            Pack8 xp;
            xp.v4[0] = *(const float4*)&scrT[d * STR];
            xp.v4[1] = *(const float4*)&scrT[d * STR + 4];
            const unsigned long long wq = pack2(sWq[d * D + j]);
            const unsigned long long wk = pack2(sWk[d * D + j]);
            const unsigned long long wv = pack2(sWv[d * D + j]);
            #pragma unroll
            for (int i = 0; i < 4; ++i) {
                ffma2(Q.u[i],  xp.u[i], wq);
                ffma2(K.u[i],  xp.u[i], wk);
                ffma2(Vv.u[i], xp.u[i], wv);
            }
        }
        __syncwarp();   // x tile reads done before Q/K rows overwrite it

        // ---- scatter Q,K as rows: Qrow[t][j] @0, Krow[s][j] @KB ----
        #pragma unroll
        for (int t = 0; t < T; ++t) {
            scrT[t * QS + j]      = Q.f[t];
            scrT[KB + t * QS + j] = K.f[t];
        }
        __syncwarp();

        // ---- scores: lane (tq,p) dots Q[tq]·K[2p], Q[tq]·K[2p+1] ----
        unsigned long long acc0 = 0ull, acc1 = 0ull;
        #pragma unroll
        for (int c = 0; c < 8; ++c) {
            Pack4 qv, k0, k1;
            qv.v4 = *(const float4*)&scrT[tq * QS + c * 4];
            k0.v4 = *(const float4*)&scrT[KB + (2 * p) * QS + c * 4];
            k1.v4 = *(const float4*)&scrT[KB + (2 * p + 1) * QS + c * 4];
            ffma2(acc0, qv.u[0], k0.u[0]);
            ffma2(acc0, qv.u[1], k0.u[1]);
            ffma2(acc1, qv.u[0], k1.u[0]);
            ffma2(acc1, qv.u[1], k1.u[1]);
        }
        float a0x, a0y, a1x, a1y;
        unpack2(acc0, a0x, a0y);
        unpack2(acc1, a1x, a1y);
        float slo = a0x + a0y;
        float shi = a1x + a1y;
        if (2 * p     > tq) slo = -1e30f;
        if (2 * p + 1 > tq) shi = -1e30f;

        // ---- softmax within the 4-lane quad owning row tq ----
        float m = fmaxf(slo, shi);
        m = fmaxf(m, __shfl_xor_sync(0xffffffffu, m, 1));
        m = fmaxf(m, __shfl_xor_sync(0xffffffffu, m, 2));
        float elo = __expf(slo - m);
        float ehi = __expf(shi - m);
        float den = elo + ehi;
        den += __shfl_xor_sync(0xffffffffu, den, 1);
        den += __shfl_xor_sync(0xffffffffu, den, 2);
        float inv = 1.0f / den;
        // attn stored transposed: sA[s][t] (stride 12, bank-clean)
        scrT[AB + (2 * p) * STR + tq]     = elo * inv;
        scrT[AB + (2 * p + 1) * STR + tq] = ehi * inv;
        __syncwarp();

        // ---- out = attn @ V (attn rows broadcast, V register-resident) ----
        Pack8 O;
        #pragma unroll
        for (int i = 0; i < 4; ++i) O.u[i] = 0ull;
        #pragma unroll
        for (int s = 0; s < T; ++s) {
            Pack8 A_;
            A_.v4[0] = *(const float4*)&scrT[AB + s * STR];
            A_.v4[1] = *(const float4*)&scrT[AB + s * STR + 4];
            const unsigned long long wv = pack2(Vv.f[s]);
            #pragma unroll
            for (int i = 0; i < 4; ++i)
                ffma2(O.u[i], A_.u[i], wv);
        }

        // ---- residual + LayerNorm 1 ----
        Pack8 L;
        #pragma unroll
        for (int t = 0; t < T; ++t) {
            float h = O.f[t] + X.f[t];
            float s1, s2;
            unpack2(warp_sum2(pack2f(h, h * h)), s1, s2);
            float mu  = s1 * (1.0f / D);
            float var = s2 * (1.0f / D) - mu * mu;
            L.f[t] = (h - mu) * rsqrtf(var + EPS);
        }
        __syncwarp();
        *(float4*)&scrT[j * STR]     = L.v4[0];
        *(float4*)&scrT[j * STR + 4] = L.v4[1];
        __syncwarp();

        // ---- MLP up: y1 = relu(ln1 @ W1); lane j owns cols j, j+32 ----
        Pack8 Ya, Yb;
        #pragma unroll
        for (int i = 0; i < 4; ++i) { Ya.u[i] = 0ull; Yb.u[i] = 0ull; }

        #pragma unroll
        for (int d = 0; d < D; ++d) {
            Pack8 xp;
            xp.v4[0] = *(const float4*)&scrT[d * STR];
            xp.v4[1] = *(const float4*)&scrT[d * STR + 4];
            const unsigned long long wa = pack2(sW1[d * H + j]);
            const unsigned long long wb = pack2(sW1[d * H + j + 32]);
            #pragma unroll
            for (int i = 0; i < 4; ++i) {
                ffma2(Ya.u[i], xp.u[i], wa);
                ffma2(Yb.u[i], xp.u[i], wb);
            }
        }
        #pragma unroll
        for (int i = 0; i < 8; ++i) {
            Ya.f[i] = fmaxf(Ya.f[i], 0.0f);
            Yb.f[i] = fmaxf(Yb.f[i], 0.0f);
        }
        __syncwarp();
        *(float4*)&scrT[j * STR]            = Ya.v4[0];
        *(float4*)&scrT[j * STR + 4]        = Ya.v4[1];
        *(float4*)&scrT[(j + 32) * STR]     = Yb.v4[0];
        *(float4*)&scrT[(j + 32) * STR + 4] = Yb.v4[1];
        __syncwarp();

        // ---- MLP down: y2 = y1 @ W2 ----
        Pack8 Y2;
        #pragma unroll
        for (int i = 0; i < 4; ++i) Y2.u[i] = 0ull;

        #pragma unroll
        for (int h = 0; h < H; ++h) {
            Pack8 xp;
            xp.v4[0] = *(const float4*)&scrT[h * STR];
            xp.v4[1] = *(const float4*)&scrT[h * STR + 4];
            const unsigned long long w = pack2(sW2[h * D + j]);
            #pragma unroll
            for (int i = 0; i < 4; ++i)
                ffma2(Y2.u[i], xp.u[i], w);
        }

        // ---- residual + LayerNorm 2 ----
        Pack8 Z;
        #pragma unroll
        for (int t = 0; t < T; ++t) {
            float h = Y2.f[t] + L.f[t];
            float s1, s2;
            unpack2(warp_sum2(pack2f(h, h * h)), s1, s2);
            float mu  = s1 * (1.0f / D);
            float var = s2 * (1.0f / D) - mu * mu;
            Z.f[t] = (h - mu) * rsqrtf(var + EPS);
        }
        __syncwarp();
        *(float4*)&scrT[j * STR]     = Z.v4[0];
        *(float4*)&scrT[j * STR + 4] = Z.v4[1];
        __syncwarp();

        // ---- logits = z @ Wout (padded to 32 cols) ----
        Pack8 Lg;
        #pragma unroll
        for (int i = 0; i < 4; ++i) Lg.u[i] = 0ull;

        #pragma unroll
        for (int d = 0; d < D; ++d) {
            Pack8 xp;
            xp.v4[0] = *(const float4*)&scrT[d * STR];
            xp.v4[1] = *(const float4*)&scrT[d * STR + 4];
            const unsigned long long w = pack2(sWo[d * 32 + j]);
            #pragma unroll
            for (int i = 0; i < 4; ++i)
                ffma2(Lg.u[i], xp.u[i], w);
        }
        __syncwarp();   // scrT reused next iteration

        if (j < V) {
            const size_t base = (size_t)b * (T * V);
            #pragma unroll
            for (int t = 0; t < T; ++t)
                out[base + t * V + j] = Lg.f[t];
        }
    }
}

extern "C" void kernel_launch(void* const* d_in, const int* in_sizes, int n_in,
                              void* d_out, int out_size)
{
    const int*   tokens  = (const int*)  d_in[0];
    const float* tok_emb = (const float*)d_in[1];
    const float* pos_emb = (const float*)d_in[2];
    const float* Wq      = (const float*)d_in[3];
    const float* Wk      = (const float*)d_in[4];
    const float* Wv      = (const float*)d_in[5];
    const float* W1      = (const float*)d_in[6];
    const float* W2      = (const float*)d_in[7];
    const float* Wout    = (const float*)d_in[8];
    float* out = (float*)d_out;

    const int nB = in_sizes[0] / T;
    const int nwarps_total = GRID * NWARP;

    mt_kernel<<<GRID, NWARP * 32>>>(tokens, tok_emb, pos_emb,
                                    Wq, Wk, Wv, W1, W2, Wout,
                                    out, nB, nwarps_total);
}